// round 17
// baseline (speedup 1.0000x reference)
#include <cuda_runtime.h>
#include <cuda_fp16.h>
#include <cstdint>

// BinaryConv2d via warp-level HMMA implicit GEMM (mma.sync m16n8k16 f16).
// R17 = R16 (single-fp16, ldmatrix.x4/tap, 1 barrier/iter, 5-slot ring,
// cross-iteration LDG/STS pipelining) +
//   - 16 output rows per block (half the prologues, -3% halo traffic)
//   - launch_bounds(128, 6): 6 blocks/SM for more memory parallelism

#define OUT_HW   512
#define CSTRIDE  48
#define ODD_OFS  3120            // 65 * 48, 16B-aligned
#define ROWBYTES 6192            // 3120 + 64*48
#define NRING    5
#define YROWS    16

__device__ __forceinline__ void ldmx4(uint32_t* r, uint32_t addr) {
    asm("ldmatrix.sync.aligned.m8n8.x4.shared.b16 {%0,%1,%2,%3}, [%4];"
        : "=r"(r[0]), "=r"(r[1]), "=r"(r[2]), "=r"(r[3])
        : "r"(addr));
}

struct SR {                       // one staged row in registers
    float2 a2[4], b2[4];
    float  a0, b0;
};

__global__ void __launch_bounds__(128, 6)
binconv_mma(const float* __restrict__ x,
            const float* __restrict__ w,
            float* __restrict__ out) {
    __shared__ __align__(16) unsigned char s_x[NRING * ROWBYTES];   // 30960 B

    const int tid  = threadIdx.x;
    const int wrp  = tid >> 5;
    const int lane = tid & 31;
    const int g    = lane >> 2;
    const int i4   = lane & 3;

    const int n   = blockIdx.z;
    const int x0  = blockIdx.x * 64;
    const int oy0 = blockIdx.y * YROWS;
    const int gx0 = 2 * x0 - 1;       // global input col of tile col 0

    const float* xn = x + ((size_t)n << 24);

    // ---- A fragments: signs as fp16 +/-1, register-resident ----
    uint32_t sA[9][4];
    #pragma unroll
    for (int tap = 0; tap < 9; ++tap) {
        #pragma unroll
        for (int q = 0; q < 4; ++q) {
            int oc = g + (q & 1) * 8;
            int c  = 2 * i4 + (q >> 1) * 8;
            uint32_t lo = (w[oc * 144 + c * 9 + tap]       == 1.f) ? 0x3C00u : 0xBC00u;
            uint32_t hi = (w[oc * 144 + (c + 1) * 9 + tap] == 1.f) ? 0x3C00u : 0xBC00u;
            sA[tap][q] = lo | (hi << 16);
        }
    }

    // ---- staging split into LDG half and cvt+STS half ----
    auto ldg_row = [&](int ia, SR& s) {
        const int cp = tid >> 4;
        const float* p0 = xn + ((size_t)(2 * cp) << 20)
                             + ((size_t)(ia < 0 ? 0 : ia) << 10);
        const float* p1 = p0 + (1 << 20);
        const bool rv = (ia >= 0);
        if ((tid & 15) == 0) {
            bool ok = rv && (gx0 >= 0);
            s.a0 = ok ? p0[gx0] : 0.f;
            s.b0 = ok ? p1[gx0] : 0.f;
        }
        #pragma unroll
        for (int v = 0; v < 4; ++v) {
            int m  = (tid & 15) + 16 * v;
            int gx = 2 * x0 + 2 * m;
            s.a2[v] = rv ? *(const float2*)(p0 + gx) : make_float2(0.f, 0.f);
            s.b2[v] = rv ? *(const float2*)(p1 + gx) : make_float2(0.f, 0.f);
        }
    };
    auto sts_row = [&](int ia, const SR& s) {
        unsigned char* rb = s_x + ((ia + NRING * 64) % NRING) * ROWBYTES;
        const int cp = tid >> 4;
        if ((tid & 15) == 0)
            *(__half2*)(rb + cp * 4) = __floats2half2_rn(s.a0, s.b0);
        #pragma unroll
        for (int v = 0; v < 4; ++v) {
            int m = (tid & 15) + 16 * v;
            *(__half2*)(rb + ODD_OFS + m * CSTRIDE + cp * 4) =
                __floats2half2_rn(s.a2[v].x, s.b2[v].x);       // tile col 1+2m
            *(__half2*)(rb + (m + 1) * CSTRIDE + cp * 4) =
                __floats2half2_rn(s.a2[v].y, s.b2[v].y);       // tile col 2+2m
        }
    };

    uint32_t sbase;
    asm("{ .reg .u64 t; cvta.to.shared.u64 t, %1; cvt.u32.u64 %0, t; }"
        : "=r"(sbase) : "l"((const void*)s_x));
    const uint32_t pslot =
        (uint32_t)(wrp * 16 + (lane & 7) + ((lane >> 4) << 3));
    const uint32_t lane_off = pslot * CSTRIDE + (uint32_t)((lane >> 3) & 1) * 16u;
    const uint32_t offj[3] = { 0u, (uint32_t)ODD_OFS, (uint32_t)CSTRIDE };

    // ---- prologue: stage rows for it=0 ----
    {
        const int iy0 = 2 * oy0 - 1;
        SR r0, r1;
        ldg_row(iy0,     r0);
        ldg_row(iy0 + 1, r1);
        sts_row(iy0,     r0);
        sts_row(iy0 + 1, r1);
        ldg_row(iy0 + 2, r0);
        sts_row(iy0 + 2, r0);
    }
    __syncthreads();

    #pragma unroll 1
    for (int it = 0; it < YROWS; ++it) {
        const int oy  = oy0 + it;
        const int iy0 = 2 * oy - 1;

        // (1) issue LDGs for it+1's two new rows (latency hidden by compute)
        SR r0, r1;
        if (it < YROWS - 1) {
            ldg_row(iy0 + 3, r0);
            ldg_row(iy0 + 4, r1);
        }

        // (2) compute it from ring slots iy0..iy0+2
        uint32_t rb3[3];
        #pragma unroll
        for (int r = 0; r < 3; ++r)
            rb3[r] = sbase
                   + (uint32_t)(((iy0 + r + NRING * 64) % NRING) * ROWBYTES)
                   + lane_off;

        float acc[2][4];
        #pragma unroll
        for (int nc = 0; nc < 2; ++nc)
            acc[nc][0] = acc[nc][1] = acc[nc][2] = acc[nc][3] = 0.f;

        #pragma unroll
        for (int tap = 0; tap < 9; ++tap) {
            uint32_t bb[4];
            ldmx4(bb, rb3[tap / 3] + offj[tap % 3]);
            asm("mma.sync.aligned.m16n8k16.row.col.f32.f16.f16.f32 "
                "{%0,%1,%2,%3}, {%4,%5,%6,%7}, {%8,%9}, {%0,%1,%2,%3};"
                : "+f"(acc[0][0]), "+f"(acc[0][1]), "+f"(acc[0][2]), "+f"(acc[0][3])
                : "r"(sA[tap][0]), "r"(sA[tap][1]), "r"(sA[tap][2]), "r"(sA[tap][3]),
                  "r"(bb[0]), "r"(bb[1]));
            asm("mma.sync.aligned.m16n8k16.row.col.f32.f16.f16.f32 "
                "{%0,%1,%2,%3}, {%4,%5,%6,%7}, {%8,%9}, {%0,%1,%2,%3};"
                : "+f"(acc[1][0]), "+f"(acc[1][1]), "+f"(acc[1][2]), "+f"(acc[1][3])
                : "r"(sA[tap][0]), "r"(sA[tap][1]), "r"(sA[tap][2]), "r"(sA[tap][3]),
                  "r"(bb[2]), "r"(bb[3]));
        }

        // ---- store: regs 0,1 -> oc=g ; regs 2,3 -> oc=g+8 ----
        #pragma unroll
        for (int nc = 0; nc < 2; ++nc) {
            int px = x0 + wrp * 16 + nc * 8 + 2 * i4;
            float* o0 = out + (((size_t)(n * 16 + g) * OUT_HW) + oy) * OUT_HW + px;
            float* o1 = o0 + (size_t)8 * OUT_HW * OUT_HW;
            *(float2*)o0 = make_float2(acc[nc][0], acc[nc][1]);
            *(float2*)o1 = make_float2(acc[nc][2], acc[nc][3]);
        }

        // (3) cvt+STS it+1's rows into slots last read at it-1 (WAR-safe)
        if (it < YROWS - 1) {
            sts_row(iy0 + 3, r0);
            sts_row(iy0 + 4, r1);
        }

        // (4) single barrier: staged rows visible, ring reuse ordered
        __syncthreads();
    }
}

extern "C" void kernel_launch(void* const* d_in, const int* in_sizes, int n_in,
                              void* d_out, int out_size) {
    const float* x = (const float*)d_in[0];
    const float* w = (const float*)d_in[1];
    float* out = (float*)d_out;

    dim3 grid(8, 512 / YROWS, 8);   // (8, 32, 8) = 2048 blocks
    dim3 block(128);
    binconv_mma<<<grid, block>>>(x, w, out);
}